// round 7
// baseline (speedup 1.0000x reference)
#include <cuda_runtime.h>
#include <cuda_fp16.h>

// RROIAlign via fp16-NHWC re-layout + cp.async-pipelined gather.
// K1: NCHW f32 -> NHWC half (near DRAM/L2 floor, unchanged).
// K2: gather. Descriptors in smem; loads staged global->smem with cp.async
//     (LDGSTS: no register cost -> deep MLP, hides L2 latency that pinned
//     the LDG versions at ~27us). Round = 8 bins (8 warps x 1 bin); 16KB
//     stage, double-buffered, one-round lookahead. Consumer: lane=(sample,
//     8ch), LDS.128 per corner, HFMA2 combine, shuffle sample-reduction,
//     fp32 stage -> coalesced writeout.

#define FB 2
#define FC 256
#define FH 200
#define FW 200
#define PER_ROI 12544      // 256*49

#define BUF_BYTES   16384                  // 128 chunks * 128B
#define ACC_WORDS   (49 * 68)              // stride 68 (16B-aligned rows)
#define SMEM_ACC    (2 * BUF_BYTES)
#define SMEM_WHW    (SMEM_ACC + ACC_WORDS * 4 + 16)
#define SMEM_BASE   (SMEM_WHW + 196 * 16)
#define SMEM_TOTAL  (SMEM_BASE + 196 * 4)

__device__ __half g_h[(size_t)FB * FH * FW * FC];   // 41 MB scratch

static __device__ __forceinline__ __half2 u2h(unsigned u) {
    __half2 h; *reinterpret_cast<unsigned*>(&h) = u; return h;
}
static __device__ __forceinline__ unsigned h2u(__half2 h) {
    return *reinterpret_cast<unsigned*>(&h);
}

// ---------------- transpose NCHW f32 -> NHWC half ----------------
__global__ void __launch_bounds__(256) transpose_kernel(const float* __restrict__ feat)
{
    __shared__ unsigned tile2[32][33];     // [w][cpair]
    const int tx = threadIdx.x;
    const int ty = threadIdx.y;
    const int w0 = blockIdx.x * 32;
    const int h  = blockIdx.y;
    const int z  = blockIdx.z;             // b*4 + ctile
    const int b  = z >> 2;
    const int c0 = (z & 3) * 64;

    const int w = w0 + tx;
#pragma unroll
    for (int k = 0; k < 4; ++k) {
        const int cp = ty + 8 * k;
        const int c  = c0 + 2 * cp;
        if (w < FW) {
            const float f0 = feat[(((size_t)b * FC + c)     * FH + h) * FW + w];
            const float f1 = feat[(((size_t)b * FC + c + 1) * FH + h) * FW + w];
            const __half2 v = __floats2half2_rn(f0, f1);
            tile2[tx][cp] = *(const unsigned*)&v;
        }
    }
    __syncthreads();
#pragma unroll
    for (int k = 0; k < 4; ++k) {
        const int wl = ty + 8 * k;
        const int w2 = w0 + wl;
        if (w2 < FW)
            ((unsigned*)g_h)[(((size_t)b * FH + h) * FW + w2) * (FC / 2) + c0 / 2 + tx]
                = tile2[wl][tx];
    }
}

// ---------------- gather ----------------
__global__ void __launch_bounds__(256, 4) gather_kernel(
    const float* __restrict__ rois,
    float* __restrict__ out)
{
    extern __shared__ __align__(16) char smem[];
    char*     s_buf  = smem;                              // 2 x 16KB stages
    float*    s_acc  = (float*)(smem + SMEM_ACC);         // [49][68]
    unsigned* s_whw  = (unsigned*)(smem + SMEM_WHW);      // 196 x 4 half2 words
    int*      s_base = (int*)(smem + SMEM_BASE);          // 196 base offsets

    const int n   = blockIdx.x >> 2;           // roi
    const int ch0 = (blockIdx.x & 3) * 64;     // channel quarter
    const int tid = threadIdx.x;

    // ---- descriptors: 196 (bin, sample) ----
    if (tid < 196) {
        const float* r = rois + n * 6;
        const int   b  = (int)r[0];
        const float cx = r[1] * 0.25f;
        const float cy = r[2] * 0.25f;
        const float rw = fmaxf(r[3] * 0.25f, 1.0f);
        const float rh = fmaxf(r[4] * 0.25f, 1.0f);
        float st, ct;
        __sincosf(r[5], &st, &ct);

        const float bin_w = rw * (1.0f / 7.0f);
        const float bin_h = rh * (1.0f / 7.0f);

        const int p  = tid >> 2;        // bin 0..48
        const int s  = tid & 3;         // sample 0..3
        const int ph = p / 7;
        const int pw = p - ph * 7;
        const float fh = ((float)(s >> 1) + 0.5f) * 0.5f;
        const float fw = ((float)(s & 1)  + 0.5f) * 0.5f;

        const float yy = -rh * 0.5f + ((float)ph + fh) * bin_h;
        const float xx = -rw * 0.5f + ((float)pw + fw) * bin_w;

        float x = xx * ct + yy * st + cx;
        float y = yy * ct - xx * st + cy;

        const bool valid = (y > -1.0f) && (y < (float)FH) &&
                           (x > -1.0f) && (x < (float)FW);

        y = fminf(fmaxf(y, 0.0f), (float)(FH - 1));
        x = fminf(fmaxf(x, 0.0f), (float)(FW - 1));

        const float y0f = fminf(floorf(y), (float)(FH - 2));
        const float x0f = fminf(floorf(x), (float)(FW - 2));

        const float ly = y - y0f;
        const float lx = x - x0f;
        const float hy = 1.0f - ly;
        const float hx = 1.0f - lx;
        const float m  = valid ? 0.25f : 0.0f;

        s_base[tid] = ((b * FH + (int)y0f) * FW + (int)x0f) * FC + ch0;
        s_whw[tid * 4 + 0] = h2u(__float2half2_rn(hy * hx * m));   // (y0,x0)
        s_whw[tid * 4 + 1] = h2u(__float2half2_rn(hy * lx * m));   // (y0,x1)
        s_whw[tid * 4 + 2] = h2u(__float2half2_rn(ly * hx * m));   // (y1,x0)
        s_whw[tid * 4 + 3] = h2u(__float2half2_rn(ly * lx * m));   // (y1,x1)
    }

    // ---- producer per-thread slot precompute (4 x 16B per round) ----
    // slot = i*256 + tid; chunk = slot/8 (128B); lane16 = slot%8.
    // chunk = b8*16 + s*4 + c  (b8: bin-in-round, s: sample, c: corner)
    int      dro[4];     // desc offset within round (b8*4 + s)
    int      b8v[4];
    long long cof[4];    // corner byte offset + lane16*16
    unsigned dsto[4];    // smem dst offset within stage
    const long long cob[4] = { 0, FC * 2,
                               (long long)FW * FC * 2,
                               (long long)FW * FC * 2 + FC * 2 };
#pragma unroll
    for (int i = 0; i < 4; ++i) {
        const int slot  = i * 256 + tid;
        const int chunk = slot >> 3;
        const int l16   = slot & 7;
        const int b8    = chunk >> 4;
        const int s     = (chunk >> 2) & 3;
        const int c     = chunk & 3;
        dro[i]  = b8 * 4 + s;
        b8v[i]  = b8;
        cof[i]  = cob[c] + l16 * 16;
        dsto[i] = (unsigned)(chunk * 128 + l16 * 16);
    }
    const unsigned buf_s0 = (unsigned)__cvta_generic_to_shared(s_buf);

    __syncthreads();   // descriptors ready

#define PRODUCE(rr, sel)                                                        \
    {                                                                           \
        const unsigned bs = buf_s0 + (sel) * BUF_BYTES;                         \
        _Pragma("unroll")                                                       \
        for (int i = 0; i < 4; ++i) {                                           \
            if ((rr) * 8 + b8v[i] < 49) {                                       \
                const char* src = (const char*)g_h                              \
                    + (long long)s_base[(rr) * 32 + dro[i]] * 2 + cof[i];       \
                asm volatile("cp.async.cg.shared.global [%0], [%1], 16;\n"      \
                             :: "r"(bs + dsto[i]), "l"(src) : "memory");        \
            }                                                                   \
        }                                                                       \
        asm volatile("cp.async.commit_group;\n" ::: "memory");                  \
    }

    PRODUCE(0, 0)

    const int wid  = tid >> 5;
    const int lane = tid & 31;
    const int q8   = lane & 7;
    const int sl   = lane >> 3;

#pragma unroll 1
    for (int r = 0; r < 7; ++r) {
        if (r < 6) {
            PRODUCE(r + 1, (r + 1) & 1)
            asm volatile("cp.async.wait_group 1;\n" ::: "memory");
        } else {
            asm volatile("cp.async.wait_group 0;\n" ::: "memory");
        }
        __syncthreads();

        const int bin = r * 8 + wid;
        if (bin < 49) {
            const char* bb = s_buf + (r & 1) * BUF_BYTES
                           + ((wid * 16 + sl * 4) << 7) + q8 * 16;
            const uint4 d0 = *(const uint4*)(bb);
            const uint4 d1 = *(const uint4*)(bb + 128);
            const uint4 d2 = *(const uint4*)(bb + 256);
            const uint4 d3 = *(const uint4*)(bb + 384);
            const int wb = (bin * 4 + sl) * 4;
            const __half2 w0 = u2h(s_whw[wb + 0]);
            const __half2 w1 = u2h(s_whw[wb + 1]);
            const __half2 w2 = u2h(s_whw[wb + 2]);
            const __half2 w3 = u2h(s_whw[wb + 3]);
            const unsigned* p0 = &d0.x;
            const unsigned* p1 = &d1.x;
            const unsigned* p2 = &d2.x;
            const unsigned* p3 = &d3.x;

            float f[8];
#pragma unroll
            for (int j = 0; j < 4; ++j) {
                __half2 t = __hmul2(w0, u2h(p0[j]));
                t = __hfma2(w1, u2h(p1[j]), t);
                t = __hfma2(w2, u2h(p2[j]), t);
                t = __hfma2(w3, u2h(p3[j]), t);
                // sample pair-sum (sl ^ 2) in half
                t = __hadd2(t, u2h(__shfl_xor_sync(0xFFFFFFFFu, h2u(t), 16)));
                const float2 ff = __half22float2(t);
                f[2 * j]     = ff.x;
                f[2 * j + 1] = ff.y;
            }
#pragma unroll
            for (int k = 0; k < 8; ++k)
                f[k] += __shfl_xor_sync(0xFFFFFFFFu, f[k], 8);

            if (sl == 0) {
                float* dst = s_acc + bin * 68 + q8 * 8;
                *(float4*)dst       = make_float4(f[0], f[1], f[2], f[3]);
                *(float4*)(dst + 4) = make_float4(f[4], f[5], f[6], f[7]);
            }
        }
        __syncthreads();
    }

    // ---- coalesced writeout: out[n][ch0+c][bin] ----
    float* ob = out + n * PER_ROI + ch0 * 49;
#pragma unroll
    for (int i = tid; i < 64 * 49; i += 256) {
        const int c  = i / 49;
        const int bn = i - c * 49;
        ob[i] = s_acc[bn * 68 + c];
    }
}

extern "C" void kernel_launch(void* const* d_in, const int* in_sizes, int n_in,
                              void* d_out, int out_size)
{
    const float* feat = (const float*)d_in[0];   // (2,256,200,200)
    const float* rois = (const float*)d_in[1];   // (512,6)
    float* out = (float*)d_out;                  // (512,256,7,7)

    const int n_rois = in_sizes[1] / 6;          // 512

    cudaFuncSetAttribute(gather_kernel,
                         cudaFuncAttributeMaxDynamicSharedMemorySize, SMEM_TOTAL);

    transpose_kernel<<<dim3(7, FH, FB * 4), dim3(32, 8)>>>(feat);
    gather_kernel<<<n_rois * 4, 256, SMEM_TOTAL>>>(rois, out);
}

// round 8
// speedup vs baseline: 1.1748x; 1.1748x over previous
#include <cuda_runtime.h>
#include <cuda_fp16.h>

// RROIAlign via fp16-NHWC re-layout (reverted from cp.async — LDGSTS issue
// cost + pipeline bubbles regressed R7).
// K1: NCHW f32 -> NHWC half.
// K2: gather; thread owns TWO bins processed fused: per sample-step it issues
//     8 independent LDG.128 (4 corners x 2 bins) -> wide MLP window.
//     launch_bounds(256,4) gives the register headroom to keep them in
//     flight. HFMA2 combine, fp32 cross-sample accumulate, smem staging,
//     coalesced writeout.

#define FB 2
#define FC 256
#define FH 200
#define FW 200
#define PER_ROI 12544      // 256*49

__device__ __half g_h[(size_t)FB * FH * FW * FC];   // 41 MB scratch

static __device__ __forceinline__ __half2 u2h(unsigned u) {
    __half2 h; *reinterpret_cast<unsigned*>(&h) = u; return h;
}

// ---------------- transpose NCHW f32 -> NHWC half ----------------
__global__ void __launch_bounds__(256) transpose_kernel(const float* __restrict__ feat)
{
    __shared__ unsigned tile2[32][33];     // [w][cpair]
    const int tx = threadIdx.x;
    const int ty = threadIdx.y;
    const int w0 = blockIdx.x * 32;
    const int h  = blockIdx.y;
    const int z  = blockIdx.z;             // b*4 + ctile
    const int b  = z >> 2;
    const int c0 = (z & 3) * 64;

    const int w = w0 + tx;
#pragma unroll
    for (int k = 0; k < 4; ++k) {
        const int cp = ty + 8 * k;
        const int c  = c0 + 2 * cp;
        if (w < FW) {
            const float f0 = feat[(((size_t)b * FC + c)     * FH + h) * FW + w];
            const float f1 = feat[(((size_t)b * FC + c + 1) * FH + h) * FW + w];
            const __half2 v = __floats2half2_rn(f0, f1);
            tile2[tx][cp] = *(const unsigned*)&v;
        }
    }
    __syncthreads();
#pragma unroll
    for (int k = 0; k < 4; ++k) {
        const int wl = ty + 8 * k;
        const int w2 = w0 + wl;
        if (w2 < FW)
            ((unsigned*)g_h)[(((size_t)b * FH + h) * FW + w2) * (FC / 2) + c0 / 2 + tx]
                = tile2[wl][tx];
    }
}

// ---------------- gather ----------------
__global__ void __launch_bounds__(256, 4) gather_kernel(
    const float* __restrict__ rois,
    float* __restrict__ out)
{
    __shared__ int   s_base[196];
    __shared__ uint4 s_wh[196];            // 4x half2-broadcast weights
    __shared__ float s_acc[49][8][9];      // [bin][q8][8 ch + pad]

    const int n   = blockIdx.x >> 2;           // roi
    const int ch0 = (blockIdx.x & 3) * 64;     // channel quarter
    const int tid = threadIdx.x;

    if (tid < 196) {
        const float* r = rois + n * 6;
        const int   b  = (int)r[0];
        const float cx = r[1] * 0.25f;
        const float cy = r[2] * 0.25f;
        const float rw = fmaxf(r[3] * 0.25f, 1.0f);
        const float rh = fmaxf(r[4] * 0.25f, 1.0f);
        float st, ct;
        __sincosf(r[5], &st, &ct);

        const float bin_w = rw * (1.0f / 7.0f);
        const float bin_h = rh * (1.0f / 7.0f);

        const int p  = tid >> 2;        // bin 0..48
        const int s  = tid & 3;         // sample 0..3
        const int ph = p / 7;
        const int pw = p - ph * 7;
        const float fh = ((float)(s >> 1) + 0.5f) * 0.5f;
        const float fw = ((float)(s & 1)  + 0.5f) * 0.5f;

        const float yy = -rh * 0.5f + ((float)ph + fh) * bin_h;
        const float xx = -rw * 0.5f + ((float)pw + fw) * bin_w;

        float x = xx * ct + yy * st + cx;
        float y = yy * ct - xx * st + cy;

        const bool valid = (y > -1.0f) && (y < (float)FH) &&
                           (x > -1.0f) && (x < (float)FW);

        y = fminf(fmaxf(y, 0.0f), (float)(FH - 1));
        x = fminf(fmaxf(x, 0.0f), (float)(FW - 1));

        const float y0f = fminf(floorf(y), (float)(FH - 2));
        const float x0f = fminf(floorf(x), (float)(FW - 2));

        const float ly = y - y0f;
        const float lx = x - x0f;
        const float hy = 1.0f - ly;
        const float hx = 1.0f - lx;
        const float m  = valid ? 0.25f : 0.0f;

        s_base[tid] = ((b * FH + (int)y0f) * FW + (int)x0f) * FC + ch0;

        const __half2 h00 = __float2half2_rn(hy * hx * m);
        const __half2 h01 = __float2half2_rn(hy * lx * m);
        const __half2 h10 = __float2half2_rn(ly * hx * m);
        const __half2 h11 = __float2half2_rn(ly * lx * m);
        uint4 wq;
        wq.x = *(const unsigned*)&h00;
        wq.y = *(const unsigned*)&h01;
        wq.z = *(const unsigned*)&h10;
        wq.w = *(const unsigned*)&h11;
        s_wh[tid] = wq;
    }
    __syncthreads();

    const int q8  = tid & 7;            // 8-channel group
    const int sub = (tid >> 3) & 3;     // bin sub-index within warp
    const int wid = tid >> 5;           // warp id 0..7

    const int binA = wid * 4 + sub;            // 0..31 (always valid)
    const int binB = 32 + binA;                // 32..63
    const bool vB  = (binB < 49);
    const int dA   = binA * 4;
    const int dB   = vB ? binB * 4 : 0;        // invalid -> reuse bin0 (L1 hit)

    float accA[8] = {0.f,0.f,0.f,0.f,0.f,0.f,0.f,0.f};
    float accB[8] = {0.f,0.f,0.f,0.f,0.f,0.f,0.f,0.f};

#pragma unroll
    for (int s = 0; s < 4; ++s) {
        const int   baseA = s_base[dA + s] + 8 * q8;
        const int   baseB = s_base[dB + s] + 8 * q8;
        const uint4 wqA   = s_wh[dA + s];
        const uint4 wqB   = s_wh[dB + s];

        // 8 independent LDG.128 issued up front
        const uint4 ra0 = __ldg((const uint4*)(g_h + baseA));
        const uint4 ra1 = __ldg((const uint4*)(g_h + baseA + FC));
        const uint4 ra2 = __ldg((const uint4*)(g_h + baseA + FW * FC));
        const uint4 ra3 = __ldg((const uint4*)(g_h + baseA + FW * FC + FC));
        const uint4 rb0 = __ldg((const uint4*)(g_h + baseB));
        const uint4 rb1 = __ldg((const uint4*)(g_h + baseB + FC));
        const uint4 rb2 = __ldg((const uint4*)(g_h + baseB + FW * FC));
        const uint4 rb3 = __ldg((const uint4*)(g_h + baseB + FW * FC + FC));

        const unsigned* pa0 = &ra0.x;  const unsigned* pa1 = &ra1.x;
        const unsigned* pa2 = &ra2.x;  const unsigned* pa3 = &ra3.x;
        const unsigned* pb0 = &rb0.x;  const unsigned* pb1 = &rb1.x;
        const unsigned* pb2 = &rb2.x;  const unsigned* pb3 = &rb3.x;

        const __half2 wa0 = u2h(wqA.x), wa1 = u2h(wqA.y),
                      wa2 = u2h(wqA.z), wa3 = u2h(wqA.w);
        const __half2 wb0 = u2h(wqB.x), wb1 = u2h(wqB.y),
                      wb2 = u2h(wqB.z), wb3 = u2h(wqB.w);

#pragma unroll
        for (int j = 0; j < 4; ++j) {
            __half2 tA = __hmul2(wa0, u2h(pa0[j]));
            tA = __hfma2(wa1, u2h(pa1[j]), tA);
            tA = __hfma2(wa2, u2h(pa2[j]), tA);
            tA = __hfma2(wa3, u2h(pa3[j]), tA);
            const float2 fA = __half22float2(tA);
            accA[2*j]   += fA.x;
            accA[2*j+1] += fA.y;

            __half2 tB = __hmul2(wb0, u2h(pb0[j]));
            tB = __hfma2(wb1, u2h(pb1[j]), tB);
            tB = __hfma2(wb2, u2h(pb2[j]), tB);
            tB = __hfma2(wb3, u2h(pb3[j]), tB);
            const float2 fB = __half22float2(tB);
            accB[2*j]   += fB.x;
            accB[2*j+1] += fB.y;
        }
    }

#pragma unroll
    for (int j = 0; j < 8; ++j)
        s_acc[binA][q8][j] = accA[j];
    if (vB) {
#pragma unroll
        for (int j = 0; j < 8; ++j)
            s_acc[binB][q8][j] = accB[j];
    }
    __syncthreads();

    // coalesced writeout: out[n][ch0+c][bin]
    float* ob = out + n * PER_ROI + ch0 * 49;
    const float* sa = &s_acc[0][0][0];
#pragma unroll
    for (int i = tid; i < 64 * 49; i += 256) {
        const int c  = i / 49;
        const int bn = i - c * 49;
        ob[i] = sa[bn * 72 + (c >> 3) * 9 + (c & 7)];
    }
}

extern "C" void kernel_launch(void* const* d_in, const int* in_sizes, int n_in,
                              void* d_out, int out_size)
{
    const float* feat = (const float*)d_in[0];   // (2,256,200,200)
    const float* rois = (const float*)d_in[1];   // (512,6)
    float* out = (float*)d_out;                  // (512,256,7,7)

    const int n_rois = in_sizes[1] / 6;          // 512

    transpose_kernel<<<dim3(7, FH, FB * 4), dim3(32, 8)>>>(feat);
    gather_kernel<<<n_rois * 4, 256>>>(rois, out);
}